// round 1
// baseline (speedup 1.0000x reference)
#include <cuda_runtime.h>

#define NN     50000
#define EE     1600000
#define IN_F   128
#define OUT_F  32
#define HH     2
#define NT_    20
#define ET_    4
#define ETE_   16
#define EAE_   16
#define ED_    16
#define DATT   96
#define SLOPE  0.2f

// Scratch (device globals: allocation-free)
__device__ float g_h[NN * OUT_F];       // 6.4 MB   node features after HeteroLinear
__device__ float g_alpha[EE * HH];      // 12.8 MB  exp(attention logits)
__device__ float g_denom[NN * HH];      // 0.4 MB   softmax denominators

__device__ __forceinline__ float lrelu(float v) { return v > 0.f ? v : SLOPE * v; }

// ---------------------------------------------------------------------------
// Zero-init output + denominators
// ---------------------------------------------------------------------------
__global__ void k_init(float* __restrict__ out) {
    int i = blockIdx.x * blockDim.x + threadIdx.x;
    if (i < NN * HH * OUT_F) out[i] = 0.f;
    if (i < NN * HH)         g_denom[i] = 0.f;
}

// ---------------------------------------------------------------------------
// HeteroLinear: h[n] = x[n] @ het_W[ntypes[n]] + het_b[ntypes[n]]
// grid = (NT, node-chunks). Block stages W_t in SMEM, compacts matching nodes,
// then warp-per-node GEMV (x row in regs, broadcast via shfl, W from SMEM).
// ---------------------------------------------------------------------------
#define NPB 1024  // nodes scanned per block
__global__ void k_het(const float* __restrict__ x, const int* __restrict__ ntypes,
                      const float* __restrict__ het_W, const float* __restrict__ het_b) {
    __shared__ float Ws[IN_F * OUT_F];   // 16 KB
    __shared__ float bs[OUT_F];
    __shared__ int   list[NPB];
    __shared__ int   cnt;

    const int t    = blockIdx.x;
    const int base = blockIdx.y * NPB;
    const int tid  = threadIdx.x;

    for (int i = tid; i < IN_F * OUT_F; i += blockDim.x)
        Ws[i] = het_W[t * IN_F * OUT_F + i];
    if (tid < OUT_F) bs[tid] = het_b[t * OUT_F + tid];
    if (tid == 0) cnt = 0;
    __syncthreads();

    const int end = min(base + NPB, NN);
    for (int n = base + tid; n < end; n += blockDim.x)
        if (ntypes[n] == t) { int p = atomicAdd(&cnt, 1); list[p] = n; }
    __syncthreads();

    const int lane = tid & 31, warp = tid >> 5, nw = blockDim.x >> 5;
    for (int i = warp; i < cnt; i += nw) {
        const int n = list[i];
        const float* xr = x + (size_t)n * IN_F;
        float x0 = xr[lane], x1 = xr[32 + lane], x2 = xr[64 + lane], x3 = xr[96 + lane];
        float acc = bs[lane];
        #pragma unroll
        for (int k = 0; k < 32; k++) {
            acc += __shfl_sync(0xffffffffu, x0, k) * Ws[ k        * OUT_F + lane];
            acc += __shfl_sync(0xffffffffu, x1, k) * Ws[(32 + k)  * OUT_F + lane];
            acc += __shfl_sync(0xffffffffu, x2, k) * Ws[(64 + k)  * OUT_F + lane];
            acc += __shfl_sync(0xffffffffu, x3, k) * Ws[(96 + k)  * OUT_F + lane];
        }
        g_h[n * OUT_F + lane] = acc;
    }
}

// ---------------------------------------------------------------------------
// Pass A: per-edge attention logits -> exp -> scratch; denominator atomics.
// One warp per edge (EPW edges per warp, consecutive).
// Softmax max-subtraction skipped: logits ~N(0,1), exp() safe in fp32 and
// mathematically identical after normalization.
// ---------------------------------------------------------------------------
#define EPW 4
__global__ void k_alpha(const int* __restrict__ ei, const int* __restrict__ etypes,
                        const float* __restrict__ eattr, const float* __restrict__ etab,
                        const float* __restrict__ eattr_W, const float* __restrict__ att_W) {
    __shared__ float aW[DATT * HH];        // 96 x 2
    __shared__ float eWs[ED_ * EAE_];      // 16 x 16
    __shared__ float etl[ET_ * ETE_];      // lrelu'd edge-type table

    const int tid = threadIdx.x;
    for (int i = tid; i < DATT * HH; i += blockDim.x) aW[i]  = att_W[i];
    for (int i = tid; i < ED_ * EAE_; i += blockDim.x) eWs[i] = eattr_W[i];
    if (tid < ET_ * ETE_) etl[tid] = lrelu(etab[tid]);
    __syncthreads();

    const int lane = tid & 31;
    const int cl   = lane & 15;
    const int gw   = blockIdx.x * (blockDim.x >> 5) + (tid >> 5);
    const long ebase = (long)gw * EPW;

    for (int j = 0; j < EPW; j++) {
        const long e = ebase + j;
        if (e >= EE) return;  // warp-uniform
        const int src = ei[e];
        const int dst = ei[EE + e];
        const int et  = etypes[e];

        const float xi = g_h[dst * OUT_F + lane];
        const float xj = g_h[src * OUT_F + lane];

        float ev = (lane < ED_) ? eattr[e * ED_ + lane] : 0.f;
        float ea = 0.f;
        #pragma unroll
        for (int k = 0; k < ED_; k++)
            ea += __shfl_sync(0xffffffffu, ev, k) * eWs[k * EAE_ + cl];
        ea = lrelu(ea);  // valid for lane < 16

        float p0 = xi * aW[lane * HH + 0] + xj * aW[(32 + lane) * HH + 0];
        float p1 = xi * aW[lane * HH + 1] + xj * aW[(32 + lane) * HH + 1];
        if (lane < 16) {
            const float te = etl[et * ETE_ + lane];
            p0 += te * aW[(64 + lane) * HH + 0] + ea * aW[(80 + lane) * HH + 0];
            p1 += te * aW[(64 + lane) * HH + 1] + ea * aW[(80 + lane) * HH + 1];
        }
        #pragma unroll
        for (int o = 16; o > 0; o >>= 1) {
            p0 += __shfl_xor_sync(0xffffffffu, p0, o);
            p1 += __shfl_xor_sync(0xffffffffu, p1, o);
        }
        if (lane == 0) {
            const float a0 = __expf(lrelu(p0));
            const float a1 = __expf(lrelu(p1));
            g_alpha[e * HH + 0] = a0;
            g_alpha[e * HH + 1] = a1;
            atomicAdd(&g_denom[dst * HH + 0], a0);
            atomicAdd(&g_denom[dst * HH + 1], a1);
        }
    }
}

// ---------------------------------------------------------------------------
// Pass B: msg = [x_j, ea] @ lin_W; out[dst, h*32+o] += msg[o] * alpha[h]/denom
// One warp per edge; lane = output channel o. 64 spread-address REDG per edge.
// ---------------------------------------------------------------------------
__global__ void k_msg(const int* __restrict__ ei, const float* __restrict__ eattr,
                      const float* __restrict__ eattr_W, const float* __restrict__ lin_W,
                      float* __restrict__ out) {
    __shared__ float lW[(OUT_F + EAE_) * OUT_F];  // 48 x 32 = 6 KB
    __shared__ float eWs[ED_ * EAE_];

    const int tid = threadIdx.x;
    for (int i = tid; i < (OUT_F + EAE_) * OUT_F; i += blockDim.x) lW[i] = lin_W[i];
    for (int i = tid; i < ED_ * EAE_; i += blockDim.x) eWs[i] = eattr_W[i];
    __syncthreads();

    const int lane = tid & 31;
    const int cl   = lane & 15;
    const int gw   = blockIdx.x * (blockDim.x >> 5) + (tid >> 5);
    const long ebase = (long)gw * EPW;

    for (int j = 0; j < EPW; j++) {
        const long e = ebase + j;
        if (e >= EE) return;
        const int src = ei[e];
        const int dst = ei[EE + e];

        const float xj = g_h[src * OUT_F + lane];

        float ev = (lane < ED_) ? eattr[e * ED_ + lane] : 0.f;
        float ea = 0.f;
        #pragma unroll
        for (int k = 0; k < ED_; k++)
            ea += __shfl_sync(0xffffffffu, ev, k) * eWs[k * EAE_ + cl];
        ea = lrelu(ea);  // valid for lane < 16

        float m = 0.f;
        #pragma unroll
        for (int k = 0; k < 32; k++)
            m += __shfl_sync(0xffffffffu, xj, k) * lW[k * OUT_F + lane];
        #pragma unroll
        for (int k = 0; k < 16; k++)
            m += __shfl_sync(0xffffffffu, ea, k) * lW[(32 + k) * OUT_F + lane];

        const float a0 = g_alpha[e * HH + 0];
        const float a1 = g_alpha[e * HH + 1];
        const float d0 = g_denom[dst * HH + 0];
        const float d1 = g_denom[dst * HH + 1];

        atomicAdd(&out[dst * (HH * OUT_F) + lane],          m * (a0 / d0));
        atomicAdd(&out[dst * (HH * OUT_F) + OUT_F + lane],  m * (a1 / d1));
    }
}

// ---------------------------------------------------------------------------
// Final ReLU in place
// ---------------------------------------------------------------------------
__global__ void k_relu(float* __restrict__ out) {
    int i = blockIdx.x * blockDim.x + threadIdx.x;
    if (i < NN * HH * OUT_F) out[i] = fmaxf(out[i], 0.f);
}

// ---------------------------------------------------------------------------
extern "C" void kernel_launch(void* const* d_in, const int* in_sizes, int n_in,
                              void* d_out, int out_size) {
    const float* x       = (const float*)d_in[0];
    const int*   ei      = (const int*)  d_in[1];   // [2, E]
    const int*   ntypes  = (const int*)  d_in[2];
    const int*   etypes  = (const int*)  d_in[3];
    const float* eattr   = (const float*)d_in[4];
    const float* het_W   = (const float*)d_in[5];
    const float* het_b   = (const float*)d_in[6];
    const float* etab    = (const float*)d_in[7];
    const float* eattr_W = (const float*)d_in[8];
    const float* att_W   = (const float*)d_in[9];
    const float* lin_W   = (const float*)d_in[10];
    float* out = (float*)d_out;

    const int total_out = NN * HH * OUT_F;
    k_init<<<(total_out + 255) / 256, 256>>>(out);

    dim3 gh(NT_, (NN + NPB - 1) / NPB);
    k_het<<<gh, 256>>>(x, ntypes, het_W, het_b);

    const int warps  = (EE + EPW - 1) / EPW;
    const int blocks = (warps + 7) / 8;   // 8 warps / 256-thread block
    k_alpha<<<blocks, 256>>>(ei, etypes, eattr, etab, eattr_W, att_W);
    k_msg<<<blocks, 256>>>(ei, eattr, eattr_W, lin_W, out);

    k_relu<<<(total_out + 255) / 256, 256>>>(out);
}

// round 2
// speedup vs baseline: 1.7261x; 1.7261x over previous
#include <cuda_runtime.h>

#define NN     50000
#define EE     1600000
#define IN_F   128
#define OUT_F  32
#define HH     2
#define NT_    20
#define ET_    4
#define ETE_   16
#define EAE_   16
#define ED_    16
#define SLOPE  0.2f

// ---- scratch (device globals; allocation-free) ----
__device__ float g_hm[NN * OUT_F];     // 6.4 MB : h @ lin_W[0:32]  (per-node msg base)
__device__ float g_att[NN * 4];        // 0.8 MB : {ai0, ai1, aj0, aj1} per node
__device__ float g_alpha[EE * 2];      // 12.8 MB: exp(logit) per edge, per head
__device__ float g_msg[EE * OUT_F];    // 204.8 MB: per-edge message vector
__device__ int   g_cnt[NN];            // per-dst edge count
__device__ int   g_off[NN];            // exclusive prefix (segment starts)
__device__ int   g_woff[NN];           // scatter write cursors
__device__ int   g_eid[EE];            // dst-sorted edge ids
__device__ int   g_bsum[64];
__device__ int   g_boff[64];

__device__ __forceinline__ float lrelu(float v) { return v > 0.f ? v : SLOPE * v; }

// ---------------------------------------------------------------------------
__global__ void k_init() {
    int i = blockIdx.x * blockDim.x + threadIdx.x;
    if (i < NN) g_cnt[i] = 0;
}

// ---------------------------------------------------------------------------
// HeteroLinear fused with all node-side precomputes:
//   h  = x @ het_W[t] + het_b[t]                (kept in registers only)
//   hm = h @ lin_W[0:32]                        (msg base)
//   ai_h = h . att_W[0:32, h]   (dst role)
//   aj_h = h . att_W[32:64, h]  (src role)
// ---------------------------------------------------------------------------
#define NPB 1024
__global__ void k_het(const float* __restrict__ x, const int* __restrict__ ntypes,
                      const float* __restrict__ het_W, const float* __restrict__ het_b,
                      const float* __restrict__ att_W, const float* __restrict__ lin_W) {
    __shared__ float Ws[IN_F * OUT_F];     // 16 KB
    __shared__ float bs[OUT_F];
    __shared__ float aWs[64 * 2];          // att_W rows 0..63
    __shared__ float lWs[OUT_F * OUT_F];   // lin_W rows 0..31
    __shared__ int   list[NPB];
    __shared__ int   cnt;

    const int t    = blockIdx.x;
    const int base = blockIdx.y * NPB;
    const int tid  = threadIdx.x;

    for (int i = tid; i < IN_F * OUT_F; i += blockDim.x) Ws[i] = het_W[t * IN_F * OUT_F + i];
    for (int i = tid; i < OUT_F * OUT_F; i += blockDim.x) lWs[i] = lin_W[i];
    if (tid < 128)   aWs[tid] = att_W[tid];
    if (tid < OUT_F) bs[tid] = het_b[t * OUT_F + tid];
    if (tid == 0)    cnt = 0;
    __syncthreads();

    const int end = min(base + NPB, NN);
    for (int n = base + tid; n < end; n += blockDim.x)
        if (ntypes[n] == t) { int p = atomicAdd(&cnt, 1); list[p] = n; }
    __syncthreads();

    const int lane = tid & 31, warp = tid >> 5, nw = blockDim.x >> 5;
    for (int i = warp; i < cnt; i += nw) {
        const int n = list[i];
        const float* xr = x + (size_t)n * IN_F;
        float x0 = xr[lane], x1 = xr[32 + lane], x2 = xr[64 + lane], x3 = xr[96 + lane];
        float acc = bs[lane];
        #pragma unroll
        for (int k = 0; k < 32; k++) {
            acc += __shfl_sync(0xffffffffu, x0, k) * Ws[ k        * OUT_F + lane];
            acc += __shfl_sync(0xffffffffu, x1, k) * Ws[(32 + k)  * OUT_F + lane];
            acc += __shfl_sync(0xffffffffu, x2, k) * Ws[(64 + k)  * OUT_F + lane];
            acc += __shfl_sync(0xffffffffu, x3, k) * Ws[(96 + k)  * OUT_F + lane];
        }
        // attention partial dots (rows 0..31 = x_i role, 32..63 = x_j role)
        float ai0 = acc * aWs[lane * 2 + 0], ai1 = acc * aWs[lane * 2 + 1];
        float aj0 = acc * aWs[64 + lane * 2 + 0], aj1 = acc * aWs[64 + lane * 2 + 1];
        #pragma unroll
        for (int o = 16; o > 0; o >>= 1) {
            ai0 += __shfl_xor_sync(0xffffffffu, ai0, o);
            ai1 += __shfl_xor_sync(0xffffffffu, ai1, o);
            aj0 += __shfl_xor_sync(0xffffffffu, aj0, o);
            aj1 += __shfl_xor_sync(0xffffffffu, aj1, o);
        }
        // msg base: h @ lin_W[0:32]
        float hm = 0.f;
        #pragma unroll
        for (int k = 0; k < 32; k++)
            hm += __shfl_sync(0xffffffffu, acc, k) * lWs[k * OUT_F + lane];
        g_hm[n * OUT_F + lane] = hm;
        if (lane == 0)
            *reinterpret_cast<float4*>(&g_att[n * 4]) = make_float4(ai0, ai1, aj0, aj1);
    }
}

// ---------------------------------------------------------------------------
// Fused edge pass: ea -> logit -> exp(alpha), msg = hm[src] + ea @ lin_W[32:48],
// plus dst histogram. One warp per edge, EPW edges per warp.
// Softmax max-pass skipped (logits ~N(0,1); exp safe; normalization identical).
// ---------------------------------------------------------------------------
#define EPW 4
__global__ void k_edge(const int* __restrict__ ei, const int* __restrict__ etypes,
                       const float* __restrict__ eattr, const float* __restrict__ etab,
                       const float* __restrict__ eattr_W, const float* __restrict__ att_W,
                       const float* __restrict__ lin_W) {
    __shared__ float eWs[ED_ * EAE_];      // 16x16
    __shared__ float lW2[EAE_ * OUT_F];    // lin_W rows 32..47
    __shared__ float aW80[ETE_ * 2];       // att_W rows 80..95
    __shared__ float cet[ET_ * 2];         // precombined edge-type att contribution

    const int tid = threadIdx.x;
    for (int i = tid; i < ED_ * EAE_; i += blockDim.x)   eWs[i] = eattr_W[i];
    for (int i = tid; i < EAE_ * OUT_F; i += blockDim.x) lW2[i] = lin_W[OUT_F * OUT_F + i];
    if (tid < 32) aW80[tid] = att_W[160 + tid];
    if (tid < ET_ * 2) {
        const int et = tid >> 1, h = tid & 1;
        float s = 0.f;
        for (int j = 0; j < ETE_; j++)
            s += lrelu(etab[et * ETE_ + j]) * att_W[(64 + j) * 2 + h];
        cet[tid] = s;
    }
    __syncthreads();

    const int lane = tid & 31;
    const int cl   = lane & 15;
    const long gw  = (long)blockIdx.x * (blockDim.x >> 5) + (tid >> 5);
    const long e0  = gw * EPW;

    for (int j = 0; j < EPW; j++) {
        const long e = e0 + j;
        if (e >= EE) return;  // warp-uniform
        const int src = __ldg(&ei[e]);
        const int dst = __ldg(&ei[EE + e]);
        const int et  = __ldg(&etypes[e]);

        float ev = (lane < ED_) ? eattr[e * ED_ + lane] : 0.f;
        float ea = 0.f;
        #pragma unroll
        for (int k = 0; k < ED_; k++)
            ea += __shfl_sync(0xffffffffu, ev, k) * eWs[k * EAE_ + cl];
        ea = lrelu(ea);  // valid for lane < 16

        float p0 = 0.f, p1 = 0.f;
        if (lane < ETE_) { p0 = ea * aW80[lane * 2]; p1 = ea * aW80[lane * 2 + 1]; }
        #pragma unroll
        for (int o = 16; o > 0; o >>= 1) {
            p0 += __shfl_xor_sync(0xffffffffu, p0, o);
            p1 += __shfl_xor_sync(0xffffffffu, p1, o);
        }

        float m = g_hm[src * OUT_F + lane];
        #pragma unroll
        for (int k = 0; k < EAE_; k++)
            m += __shfl_sync(0xffffffffu, ea, k) * lW2[k * OUT_F + lane];
        g_msg[e * OUT_F + lane] = m;

        if (lane == 0) {
            const float4 ad = *reinterpret_cast<const float4*>(&g_att[dst * 4]);
            const float4 as = *reinterpret_cast<const float4*>(&g_att[src * 4]);
            const float l0 = ad.x + as.z + cet[et * 2 + 0] + p0;
            const float l1 = ad.y + as.w + cet[et * 2 + 1] + p1;
            *reinterpret_cast<float2*>(&g_alpha[e * 2]) =
                make_float2(__expf(lrelu(l0)), __expf(lrelu(l1)));
            atomicAdd(&g_cnt[dst], 1);
        }
    }
}

// ---------------------------------------------------------------------------
// 3-phase exclusive scan of g_cnt -> g_off (and copy to g_woff)
// ---------------------------------------------------------------------------
__global__ void k_scan1() {   // 49 blocks x 1024
    __shared__ int ws[32];
    const int b = blockIdx.x, tid = threadIdx.x;
    const int i = b * 1024 + tid;
    int v = (i < NN) ? g_cnt[i] : 0;
    const int lane = tid & 31, w = tid >> 5;
    int incl = v;
    #pragma unroll
    for (int o = 1; o < 32; o <<= 1) {
        int t = __shfl_up_sync(0xffffffffu, incl, o);
        if (lane >= o) incl += t;
    }
    if (lane == 31) ws[w] = incl;
    __syncthreads();
    if (w == 0) {
        int s = ws[lane];
        int si = s;
        #pragma unroll
        for (int o = 1; o < 32; o <<= 1) {
            int t = __shfl_up_sync(0xffffffffu, si, o);
            if (lane >= o) si += t;
        }
        ws[lane] = si - s;
        if (lane == 31) g_bsum[b] = si;
    }
    __syncthreads();
    if (i < NN) g_off[i] = incl - v + ws[w];
}

__global__ void k_scan2(int nb) {  // 1 block
    __shared__ int s[64];
    if (threadIdx.x < nb) s[threadIdx.x] = g_bsum[threadIdx.x];
    __syncthreads();
    if (threadIdx.x == 0) {
        int c = 0;
        for (int i = 0; i < nb; i++) { int t = s[i]; s[i] = c; c += t; }
    }
    __syncthreads();
    if (threadIdx.x < nb) g_boff[threadIdx.x] = s[threadIdx.x];
}

__global__ void k_scan3() {  // 49 blocks x 1024
    const int i = blockIdx.x * 1024 + threadIdx.x;
    if (i < NN) {
        const int v = g_off[i] + g_boff[blockIdx.x];
        g_off[i] = v;
        g_woff[i] = v;
    }
}

// ---------------------------------------------------------------------------
__global__ void k_scatter(const int* __restrict__ ei) {
    const int e = blockIdx.x * blockDim.x + threadIdx.x;
    if (e >= EE) return;
    const int d = ei[EE + e];
    const int pos = atomicAdd(&g_woff[d], 1);
    g_eid[pos] = e;
}

// ---------------------------------------------------------------------------
// Aggregation: one warp per dst node over its sorted edge segment.
// Denominator accumulated in the same loop; division + ReLU folded at the end.
// ---------------------------------------------------------------------------
__global__ void k_agg(float* __restrict__ out) {
    const int lane = threadIdx.x & 31;
    const int n = blockIdx.x * (blockDim.x >> 5) + (threadIdx.x >> 5);
    if (n >= NN) return;
    const int off = g_off[n], c = g_cnt[n];
    float acc0 = 0.f, acc1 = 0.f, d0 = 0.f, d1 = 0.f;
    for (int i = 0; i < c; i++) {
        const int e = __ldg(&g_eid[off + i]);
        const float2 a = *reinterpret_cast<const float2*>(&g_alpha[(size_t)e * 2]);
        const float m = g_msg[(size_t)e * OUT_F + lane];
        acc0 += m * a.x; acc1 += m * a.y;
        d0 += a.x; d1 += a.y;
    }
    const float o0 = c ? fmaxf(acc0 / d0, 0.f) : 0.f;
    const float o1 = c ? fmaxf(acc1 / d1, 0.f) : 0.f;
    out[(size_t)n * 64 + lane]      = o0;
    out[(size_t)n * 64 + 32 + lane] = o1;
}

// ---------------------------------------------------------------------------
extern "C" void kernel_launch(void* const* d_in, const int* in_sizes, int n_in,
                              void* d_out, int out_size) {
    const float* x       = (const float*)d_in[0];
    const int*   ei      = (const int*)  d_in[1];
    const int*   ntypes  = (const int*)  d_in[2];
    const int*   etypes  = (const int*)  d_in[3];
    const float* eattr   = (const float*)d_in[4];
    const float* het_W   = (const float*)d_in[5];
    const float* het_b   = (const float*)d_in[6];
    const float* etab    = (const float*)d_in[7];
    const float* eattr_W = (const float*)d_in[8];
    const float* att_W   = (const float*)d_in[9];
    const float* lin_W   = (const float*)d_in[10];
    float* out = (float*)d_out;

    k_init<<<(NN + 255) / 256, 256>>>();

    dim3 gh(NT_, (NN + NPB - 1) / NPB);
    k_het<<<gh, 256>>>(x, ntypes, het_W, het_b, att_W, lin_W);

    const int warps  = EE / EPW;          // 400000
    const int blocks = (warps + 7) / 8;   // 8 warps per 256-thread block
    k_edge<<<blocks, 256>>>(ei, etypes, eattr, etab, eattr_W, att_W, lin_W);

    const int NB = (NN + 1023) / 1024;    // 49
    k_scan1<<<NB, 1024>>>();
    k_scan2<<<1, 64>>>(NB);
    k_scan3<<<NB, 1024>>>();

    k_scatter<<<(EE + 255) / 256, 256>>>(ei);

    k_agg<<<(NN * 32 + 255) / 256, 256>>>(out);
}

// round 3
// speedup vs baseline: 2.0442x; 1.1843x over previous
#include <cuda_runtime.h>

#define NN     50000
#define EE     1600000
#define IN_F   128
#define OUT_F  32
#define NT_    20
#define ET_    4
#define ETE_   16
#define EAE_   16
#define ED_    16
#define SLOPE  0.2f

// ---- scratch (device globals; allocation-free) ----
__device__ float     g_hm[NN * OUT_F];   // 6.4 MB : h @ lin_W[0:32]  (L2-resident)
__device__ float     g_att[NN * 4];      // 0.8 MB : {ai0, ai1, aj0, aj1}
__device__ long long g_erec[EE];         // 12.8 MB: dst-sorted {e, src|et<<16}
__device__ int       g_cnt[NN];
__device__ int       g_off[NN];
__device__ int       g_woff[NN];
__device__ int       g_bsum[64];

__device__ __forceinline__ float lrelu(float v) { return v > 0.f ? v : SLOPE * v; }

// ---------------------------------------------------------------------------
__global__ void k_init() {
    int i = blockIdx.x * blockDim.x + threadIdx.x;
    if (i < NN) g_cnt[i] = 0;
}

// ---------------------------------------------------------------------------
// Histogram of destinations
// ---------------------------------------------------------------------------
__global__ void k_cnt(const int* __restrict__ ei) {
    int e = blockIdx.x * blockDim.x + threadIdx.x;
    if (e < EE) atomicAdd(&g_cnt[ei[EE + e]], 1);
}

// ---------------------------------------------------------------------------
// HeteroLinear + node-side precomputes:
//   h   = x @ het_W[t] + het_b[t]          (registers only)
//   hm  = h @ lin_W[0:32]
//   ai_h = h . att_W[0:32, h], aj_h = h . att_W[32:64, h]
// ---------------------------------------------------------------------------
#define NPB 1024
__global__ void k_het(const float* __restrict__ x, const int* __restrict__ ntypes,
                      const float* __restrict__ het_W, const float* __restrict__ het_b,
                      const float* __restrict__ att_W, const float* __restrict__ lin_W) {
    __shared__ float Ws[IN_F * OUT_F];
    __shared__ float bs[OUT_F];
    __shared__ float aWs[64 * 2];
    __shared__ float lWs[OUT_F * OUT_F];
    __shared__ int   list[NPB];
    __shared__ int   cnt;

    const int t    = blockIdx.x;
    const int base = blockIdx.y * NPB;
    const int tid  = threadIdx.x;

    for (int i = tid; i < IN_F * OUT_F; i += blockDim.x) Ws[i] = het_W[t * IN_F * OUT_F + i];
    for (int i = tid; i < OUT_F * OUT_F; i += blockDim.x) lWs[i] = lin_W[i];
    if (tid < 128)   aWs[tid] = att_W[tid];
    if (tid < OUT_F) bs[tid] = het_b[t * OUT_F + tid];
    if (tid == 0)    cnt = 0;
    __syncthreads();

    const int end = min(base + NPB, NN);
    for (int n = base + tid; n < end; n += blockDim.x)
        if (ntypes[n] == t) { int p = atomicAdd(&cnt, 1); list[p] = n; }
    __syncthreads();

    const int lane = tid & 31, warp = tid >> 5, nw = blockDim.x >> 5;
    for (int i = warp; i < cnt; i += nw) {
        const int n = list[i];
        const float* xr = x + (size_t)n * IN_F;
        float x0 = xr[lane], x1 = xr[32 + lane], x2 = xr[64 + lane], x3 = xr[96 + lane];
        float acc = bs[lane];
        #pragma unroll
        for (int k = 0; k < 32; k++) {
            acc += __shfl_sync(0xffffffffu, x0, k) * Ws[ k        * OUT_F + lane];
            acc += __shfl_sync(0xffffffffu, x1, k) * Ws[(32 + k)  * OUT_F + lane];
            acc += __shfl_sync(0xffffffffu, x2, k) * Ws[(64 + k)  * OUT_F + lane];
            acc += __shfl_sync(0xffffffffu, x3, k) * Ws[(96 + k)  * OUT_F + lane];
        }
        float ai0 = acc * aWs[lane * 2 + 0], ai1 = acc * aWs[lane * 2 + 1];
        float aj0 = acc * aWs[64 + lane * 2 + 0], aj1 = acc * aWs[64 + lane * 2 + 1];
        #pragma unroll
        for (int o = 16; o > 0; o >>= 1) {
            ai0 += __shfl_xor_sync(0xffffffffu, ai0, o);
            ai1 += __shfl_xor_sync(0xffffffffu, ai1, o);
            aj0 += __shfl_xor_sync(0xffffffffu, aj0, o);
            aj1 += __shfl_xor_sync(0xffffffffu, aj1, o);
        }
        float hm = 0.f;
        #pragma unroll
        for (int k = 0; k < 32; k++)
            hm += __shfl_sync(0xffffffffu, acc, k) * lWs[k * OUT_F + lane];
        g_hm[n * OUT_F + lane] = hm;
        if (lane == 0)
            *reinterpret_cast<float4*>(&g_att[n * 4]) = make_float4(ai0, ai1, aj0, aj1);
    }
}

// ---------------------------------------------------------------------------
// Scan: per-block inclusive -> block sums; block offsets folded into k_scan3.
// ---------------------------------------------------------------------------
__global__ void k_scan1() {
    __shared__ int ws[32];
    const int b = blockIdx.x, tid = threadIdx.x;
    const int i = b * 1024 + tid;
    int v = (i < NN) ? g_cnt[i] : 0;
    const int lane = tid & 31, w = tid >> 5;
    int incl = v;
    #pragma unroll
    for (int o = 1; o < 32; o <<= 1) {
        int t = __shfl_up_sync(0xffffffffu, incl, o);
        if (lane >= o) incl += t;
    }
    if (lane == 31) ws[w] = incl;
    __syncthreads();
    if (w == 0) {
        int s = ws[lane];
        int si = s;
        #pragma unroll
        for (int o = 1; o < 32; o <<= 1) {
            int t = __shfl_up_sync(0xffffffffu, si, o);
            if (lane >= o) si += t;
        }
        ws[lane] = si - s;
        if (lane == 31) g_bsum[b] = si;
    }
    __syncthreads();
    if (i < NN) g_off[i] = incl - v + ws[w];
}

__global__ void k_scan3() {
    const int b = blockIdx.x;
    __shared__ int boff;
    if (threadIdx.x == 0) {
        int s = 0;
        #pragma unroll 8
        for (int i = 0; i < b; i++) s += g_bsum[i];
        boff = s;
    }
    __syncthreads();
    const int i = b * 1024 + threadIdx.x;
    if (i < NN) {
        const int v = g_off[i] + boff;
        g_off[i] = v;
        g_woff[i] = v;
    }
}

// ---------------------------------------------------------------------------
// Scatter: dst-sorted compact records {e (hi 32), src | et<<16 (lo 32)}
// ---------------------------------------------------------------------------
__global__ void k_scatter(const int* __restrict__ ei, const int* __restrict__ etypes) {
    const int e = blockIdx.x * blockDim.x + threadIdx.x;
    if (e >= EE) return;
    const int src = ei[e];
    const int d   = ei[EE + e];
    const int et  = etypes[e];
    const int pos = atomicAdd(&g_woff[d], 1);
    g_erec[pos] = ((long long)e << 32) | (unsigned)(src | (et << 16));
}

// ---------------------------------------------------------------------------
// Fused edge+aggregate: one warp per dst node over its sorted segment.
// Per edge: ea = lrelu(eattr @ eattr_W); logit -> exp; msg = hm[src] + ea @ lW2;
// accumulate weighted sum + denominator; normalize + ReLU at the end.
// Softmax max-pass skipped (logits ~N(0,1); exp safe; normalization identical).
// ---------------------------------------------------------------------------
__global__ void k_agg(const float* __restrict__ eattr, const float* __restrict__ etab,
                      const float* __restrict__ eattr_W, const float* __restrict__ att_W,
                      const float* __restrict__ lin_W, float* __restrict__ out) {
    __shared__ float eWs[ED_ * EAE_];     // eattr_W 16x16
    __shared__ float lW2[EAE_ * OUT_F];   // lin_W rows 32..47
    __shared__ float aW80[ETE_ * 2];      // att_W rows 80..95
    __shared__ float cet[ET_ * 2];        // precombined edge-type logit term

    const int tid = threadIdx.x;
    for (int i = tid; i < ED_ * EAE_; i += blockDim.x)   eWs[i] = eattr_W[i];
    for (int i = tid; i < EAE_ * OUT_F; i += blockDim.x) lW2[i] = lin_W[OUT_F * OUT_F + i];
    if (tid < 32) aW80[tid] = att_W[160 + tid];
    if (tid < ET_ * 2) {
        const int et = tid >> 1, h = tid & 1;
        float s = 0.f;
        for (int j = 0; j < ETE_; j++)
            s += lrelu(etab[et * ETE_ + j]) * att_W[(64 + j) * 2 + h];
        cet[tid] = s;
    }
    __syncthreads();

    const int lane = tid & 31;
    const int cl   = lane & 15;
    const int n    = blockIdx.x * (blockDim.x >> 5) + (tid >> 5);
    if (n >= NN) return;

    const int off = g_off[n], c = g_cnt[n];
    const float2 adt = *reinterpret_cast<const float2*>(&g_att[n * 4]);  // ai0, ai1

    float acc0 = 0.f, acc1 = 0.f, d0 = 0.f, d1 = 0.f;

    long long rec = 0; float ev = 0.f;
    if (c > 0) {
        rec = __ldg(&g_erec[off]);
        ev  = __ldg(&eattr[((size_t)(rec >> 32)) * ED_ + cl]);
    }

    for (int i = 0; i < c; i++) {
        // prefetch next edge's record + eattr row
        long long rec_n = 0; float ev_n = 0.f;
        if (i + 1 < c) {
            rec_n = __ldg(&g_erec[off + i + 1]);
            ev_n  = __ldg(&eattr[((size_t)(rec_n >> 32)) * ED_ + cl]);
        }

        const int sp  = (int)rec;
        const int src = sp & 0xFFFF;
        const int et  = (sp >> 16) & 3;

        // node-side gathers (L2-resident tables)
        float m = g_hm[src * OUT_F + lane];
        const float2 asr = *reinterpret_cast<const float2*>(&g_att[src * 4 + 2]);  // aj0, aj1

        // ea = lrelu(eattr_row @ eattr_W)   (valid in lanes 0..15, dup 16..31)
        float eaA = 0.f, eaB = 0.f;
        #pragma unroll
        for (int k = 0; k < ED_; k += 2) {
            eaA += __shfl_sync(0xffffffffu, ev, k)     * eWs[ k      * EAE_ + cl];
            eaB += __shfl_sync(0xffffffffu, ev, k + 1) * eWs[(k + 1) * EAE_ + cl];
        }
        const float ea = lrelu(eaA + eaB);

        // attention ea-term
        float p0 = 0.f, p1 = 0.f;
        if (lane < ETE_) { p0 = ea * aW80[lane * 2]; p1 = ea * aW80[lane * 2 + 1]; }
        #pragma unroll
        for (int o = 16; o > 0; o >>= 1) {
            p0 += __shfl_xor_sync(0xffffffffu, p0, o);
            p1 += __shfl_xor_sync(0xffffffffu, p1, o);
        }

        // msg = hm[src] + ea @ lin_W[32:48]
        #pragma unroll
        for (int k = 0; k < EAE_; k++)
            m += __shfl_sync(0xffffffffu, ea, k) * lW2[k * OUT_F + lane];

        const float l0 = adt.x + asr.x + cet[et * 2 + 0] + p0;
        const float l1 = adt.y + asr.y + cet[et * 2 + 1] + p1;
        const float a0 = __expf(lrelu(l0));
        const float a1 = __expf(lrelu(l1));

        acc0 += m * a0; acc1 += m * a1;
        d0 += a0; d1 += a1;

        rec = rec_n; ev = ev_n;
    }

    const float o0 = c ? fmaxf(acc0 / d0, 0.f) : 0.f;
    const float o1 = c ? fmaxf(acc1 / d1, 0.f) : 0.f;
    out[(size_t)n * 64 + lane]      = o0;
    out[(size_t)n * 64 + 32 + lane] = o1;
}

// ---------------------------------------------------------------------------
extern "C" void kernel_launch(void* const* d_in, const int* in_sizes, int n_in,
                              void* d_out, int out_size) {
    const float* x       = (const float*)d_in[0];
    const int*   ei      = (const int*)  d_in[1];
    const int*   ntypes  = (const int*)  d_in[2];
    const int*   etypes  = (const int*)  d_in[3];
    const float* eattr   = (const float*)d_in[4];
    const float* het_W   = (const float*)d_in[5];
    const float* het_b   = (const float*)d_in[6];
    const float* etab    = (const float*)d_in[7];
    const float* eattr_W = (const float*)d_in[8];
    const float* att_W   = (const float*)d_in[9];
    const float* lin_W   = (const float*)d_in[10];
    float* out = (float*)d_out;

    k_init<<<(NN + 255) / 256, 256>>>();
    k_cnt<<<(EE + 255) / 256, 256>>>(ei);

    dim3 gh(NT_, (NN + NPB - 1) / NPB);
    k_het<<<gh, 256>>>(x, ntypes, het_W, het_b, att_W, lin_W);

    const int NB = (NN + 1023) / 1024;  // 49
    k_scan1<<<NB, 1024>>>();
    k_scan3<<<NB, 1024>>>();

    k_scatter<<<(EE + 255) / 256, 256>>>(ei, etypes);

    k_agg<<<(NN * 32 + 255) / 256, 256>>>(eattr, etab, eattr_W, att_W, lin_W, out);
}

// round 4
// speedup vs baseline: 2.5992x; 1.2715x over previous
#include <cuda_runtime.h>

#define NN     50000
#define EE     1600000
#define IN_F   128
#define OUT_F  32
#define NT_    20
#define ET_    4
#define ETE_   16
#define EAE_   16
#define ED_    16
#define SLOPE  0.2f

// ---- scratch (device globals; allocation-free) ----
__device__ float     g_hm[NN * OUT_F];   // 6.4 MB : h @ lin_W[0:32] (L2-resident)
__device__ float     g_att[NN * 4];      // 0.8 MB : {ai0, ai1, aj0, aj1}
__device__ long long g_erec[EE];         // 12.8 MB: dst-sorted {e, src|et<<16}
__device__ int       g_cnt[NN];
__device__ int       g_off[NN];
__device__ int       g_woff[NN];
__device__ int       g_bsum[64];

__device__ __forceinline__ float lrelu(float v) { return v > 0.f ? v : SLOPE * v; }

// ---------------------------------------------------------------------------
__global__ void k_init() {
    int i = blockIdx.x * blockDim.x + threadIdx.x;
    if (i < NN) g_cnt[i] = 0;
}

__global__ void k_cnt(const int* __restrict__ ei) {
    int e = blockIdx.x * blockDim.x + threadIdx.x;
    if (e < EE) atomicAdd(&g_cnt[ei[EE + e]], 1);
}

// ---------------------------------------------------------------------------
// HeteroLinear + node-side precomputes (h never leaves registers):
//   hm = h @ lin_W[0:32];  ai_h = h.att_W[0:32,h];  aj_h = h.att_W[32:64,h]
// ---------------------------------------------------------------------------
#define NPB 1024
__global__ void k_het(const float* __restrict__ x, const int* __restrict__ ntypes,
                      const float* __restrict__ het_W, const float* __restrict__ het_b,
                      const float* __restrict__ att_W, const float* __restrict__ lin_W) {
    __shared__ float Ws[IN_F * OUT_F];
    __shared__ float bs[OUT_F];
    __shared__ float aWs[64 * 2];
    __shared__ float lWs[OUT_F * OUT_F];
    __shared__ int   list[NPB];
    __shared__ int   cnt;

    const int t    = blockIdx.x;
    const int base = blockIdx.y * NPB;
    const int tid  = threadIdx.x;

    for (int i = tid; i < IN_F * OUT_F; i += blockDim.x) Ws[i] = het_W[t * IN_F * OUT_F + i];
    for (int i = tid; i < OUT_F * OUT_F; i += blockDim.x) lWs[i] = lin_W[i];
    if (tid < 128)   aWs[tid] = att_W[tid];
    if (tid < OUT_F) bs[tid] = het_b[t * OUT_F + tid];
    if (tid == 0)    cnt = 0;
    __syncthreads();

    const int end = min(base + NPB, NN);
    for (int n = base + tid; n < end; n += blockDim.x)
        if (ntypes[n] == t) { int p = atomicAdd(&cnt, 1); list[p] = n; }
    __syncthreads();

    const int lane = tid & 31, warp = tid >> 5, nw = blockDim.x >> 5;
    for (int i = warp; i < cnt; i += nw) {
        const int n = list[i];
        const float* xr = x + (size_t)n * IN_F;
        float x0 = xr[lane], x1 = xr[32 + lane], x2 = xr[64 + lane], x3 = xr[96 + lane];
        float acc = bs[lane];
        #pragma unroll
        for (int k = 0; k < 32; k++) {
            acc += __shfl_sync(0xffffffffu, x0, k) * Ws[ k        * OUT_F + lane];
            acc += __shfl_sync(0xffffffffu, x1, k) * Ws[(32 + k)  * OUT_F + lane];
            acc += __shfl_sync(0xffffffffu, x2, k) * Ws[(64 + k)  * OUT_F + lane];
            acc += __shfl_sync(0xffffffffu, x3, k) * Ws[(96 + k)  * OUT_F + lane];
        }
        float ai0 = acc * aWs[lane * 2 + 0], ai1 = acc * aWs[lane * 2 + 1];
        float aj0 = acc * aWs[64 + lane * 2 + 0], aj1 = acc * aWs[64 + lane * 2 + 1];
        #pragma unroll
        for (int o = 16; o > 0; o >>= 1) {
            ai0 += __shfl_xor_sync(0xffffffffu, ai0, o);
            ai1 += __shfl_xor_sync(0xffffffffu, ai1, o);
            aj0 += __shfl_xor_sync(0xffffffffu, aj0, o);
            aj1 += __shfl_xor_sync(0xffffffffu, aj1, o);
        }
        float hm = 0.f;
        #pragma unroll
        for (int k = 0; k < 32; k++)
            hm += __shfl_sync(0xffffffffu, acc, k) * lWs[k * OUT_F + lane];
        g_hm[n * OUT_F + lane] = hm;
        if (lane == 0)
            *reinterpret_cast<float4*>(&g_att[n * 4]) = make_float4(ai0, ai1, aj0, aj1);
    }
}

// ---------------------------------------------------------------------------
// Scan
// ---------------------------------------------------------------------------
__global__ void k_scan1() {
    __shared__ int ws[32];
    const int b = blockIdx.x, tid = threadIdx.x;
    const int i = b * 1024 + tid;
    int v = (i < NN) ? g_cnt[i] : 0;
    const int lane = tid & 31, w = tid >> 5;
    int incl = v;
    #pragma unroll
    for (int o = 1; o < 32; o <<= 1) {
        int t = __shfl_up_sync(0xffffffffu, incl, o);
        if (lane >= o) incl += t;
    }
    if (lane == 31) ws[w] = incl;
    __syncthreads();
    if (w == 0) {
        int s = ws[lane];
        int si = s;
        #pragma unroll
        for (int o = 1; o < 32; o <<= 1) {
            int t = __shfl_up_sync(0xffffffffu, si, o);
            if (lane >= o) si += t;
        }
        ws[lane] = si - s;
        if (lane == 31) g_bsum[b] = si;
    }
    __syncthreads();
    if (i < NN) g_off[i] = incl - v + ws[w];
}

__global__ void k_scan3() {
    const int b = blockIdx.x;
    __shared__ int boff;
    if (threadIdx.x == 0) {
        int s = 0;
        for (int i = 0; i < b; i++) s += g_bsum[i];
        boff = s;
    }
    __syncthreads();
    const int i = b * 1024 + threadIdx.x;
    if (i < NN) {
        const int v = g_off[i] + boff;
        g_off[i] = v;
        g_woff[i] = v;
    }
}

// ---------------------------------------------------------------------------
__global__ void k_scatter(const int* __restrict__ ei, const int* __restrict__ etypes) {
    const int e = blockIdx.x * blockDim.x + threadIdx.x;
    if (e >= EE) return;
    const int src = ei[e];
    const int d   = ei[EE + e];
    const int et  = etypes[e];
    const int pos = atomicAdd(&g_woff[d], 1);
    g_erec[pos] = ((long long)e << 32) | (unsigned)(src | (et << 16));
}

// ---------------------------------------------------------------------------
// Fused edge+aggregate, one warp per dst node.
// Per edge: ea (register GEMV, eattr row via broadcast LDG.128),
//           logit -> exp(alpha), accumulate {alpha*hm[src], alpha*ea, alpha}.
// The ea@lin_W[32:48] GEMV is hoisted out of the loop by linearity.
// Softmax max-pass skipped (logits ~N(0,1); normalization identical).
// ---------------------------------------------------------------------------
__global__ void __launch_bounds__(256) k_agg(
        const float* __restrict__ eattr, const float* __restrict__ etab,
        const float* __restrict__ eattr_W, const float* __restrict__ att_W,
        const float* __restrict__ lin_W, float* __restrict__ out) {
    __shared__ float lW2[EAE_ * OUT_F];  // lin_W rows 32..47
    __shared__ float cet[ET_ * 2];       // precombined edge-type logit term

    const int tid  = threadIdx.x;
    const int lane = tid & 31;
    const int cl   = lane & 15;

    for (int i = tid; i < EAE_ * OUT_F; i += blockDim.x) lW2[i] = lin_W[OUT_F * OUT_F + i];
    if (tid < ET_ * 2) {
        const int et = tid >> 1, h = tid & 1;
        float s = 0.f;
        for (int j = 0; j < ETE_; j++)
            s += lrelu(etab[et * ETE_ + j]) * att_W[(64 + j) * 2 + h];
        cet[tid] = s;
    }
    __syncthreads();

    // per-lane column of eattr_W in registers
    float Wr[ED_];
    #pragma unroll
    for (int k = 0; k < ED_; k++) Wr[k] = eattr_W[k * EAE_ + cl];
    // attention weight for this lane's (channel, head): head = lane>>4
    const float awh = att_W[160 + cl * 2 + (lane >> 4)];

    const int n = blockIdx.x * (blockDim.x >> 5) + (tid >> 5);
    if (n >= NN) return;

    const int off = g_off[n], c = g_cnt[n];
    const float2 adt = *reinterpret_cast<const float2*>(&g_att[n * 4]);  // ai0, ai1

    float acc0 = 0.f, acc1 = 0.f, wea0 = 0.f, wea1 = 0.f, d0 = 0.f, d1 = 0.f;

    const long long* erecp = &g_erec[off];
    long long rec = 0;
    float4 va, vb, vc, vd; float hmv = 0.f; float2 asr = make_float2(0.f, 0.f);
    if (c > 0) {
        rec = __ldg(erecp);
        const size_t e = (size_t)(rec >> 32);
        const int sp = (int)rec, src = sp & 0xFFFF;
        const float4* er = reinterpret_cast<const float4*>(&eattr[e * ED_]);
        va = __ldg(er); vb = __ldg(er + 1); vc = __ldg(er + 2); vd = __ldg(er + 3);
        hmv = g_hm[src * OUT_F + lane];
        asr = *reinterpret_cast<const float2*>(&g_att[src * 4 + 2]);
    }

    for (int i = 0; i < c; i++) {
        // prefetch next edge
        long long recn = 0;
        float4 nva, nvb, nvc, nvd; float nhm = 0.f; float2 nasr = make_float2(0.f, 0.f);
        if (i + 1 < c) {
            recn = __ldg(erecp + i + 1);
            const size_t e = (size_t)(recn >> 32);
            const int sp = (int)recn, src = sp & 0xFFFF;
            const float4* er = reinterpret_cast<const float4*>(&eattr[e * ED_]);
            nva = __ldg(er); nvb = __ldg(er + 1); nvc = __ldg(er + 2); nvd = __ldg(er + 3);
            nhm = g_hm[src * OUT_F + lane];
            nasr = *reinterpret_cast<const float2*>(&g_att[src * 4 + 2]);
        }

        // ea_j for j = cl (duplicated in upper half)
        float z = va.x * Wr[0]  + va.y * Wr[1]  + va.z * Wr[2]  + va.w * Wr[3]
                + vb.x * Wr[4]  + vb.y * Wr[5]  + vb.z * Wr[6]  + vb.w * Wr[7]
                + vc.x * Wr[8]  + vc.y * Wr[9]  + vc.z * Wr[10] + vc.w * Wr[11]
                + vd.x * Wr[12] + vd.y * Wr[13] + vd.z * Wr[14] + vd.w * Wr[15];
        const float ea = lrelu(z);

        // attention ea-term: lower half head0, upper half head1; butterfly in halves
        float v = ea * awh;
        v += __shfl_xor_sync(0xffffffffu, v, 8);
        v += __shfl_xor_sync(0xffffffffu, v, 4);
        v += __shfl_xor_sync(0xffffffffu, v, 2);
        v += __shfl_xor_sync(0xffffffffu, v, 1);
        const float p0 = __shfl_sync(0xffffffffu, v, 0);
        const float p1 = __shfl_sync(0xffffffffu, v, 16);

        const int et = ((int)rec >> 16) & 3;
        const float l0 = adt.x + asr.x + cet[et * 2 + 0] + p0;
        const float l1 = adt.y + asr.y + cet[et * 2 + 1] + p1;
        const float a0 = __expf(lrelu(l0));
        const float a1 = __expf(lrelu(l1));

        acc0 += a0 * hmv;  acc1 += a1 * hmv;
        wea0 += a0 * ea;   wea1 += a1 * ea;
        d0   += a0;        d1   += a1;

        rec = recn; va = nva; vb = nvb; vc = nvc; vd = nvd; hmv = nhm; asr = nasr;
    }

    // hoisted GEMV: out_h = (acc_h + wea_h @ lin_W[32:48]) / d_h
    float m0 = acc0, m1 = acc1;
    #pragma unroll
    for (int k = 0; k < EAE_; k++) {
        m0 += __shfl_sync(0xffffffffu, wea0, k) * lW2[k * OUT_F + lane];
        m1 += __shfl_sync(0xffffffffu, wea1, k) * lW2[k * OUT_F + lane];
    }
    out[(size_t)n * 64 + lane]      = c ? fmaxf(m0 / d0, 0.f) : 0.f;
    out[(size_t)n * 64 + 32 + lane] = c ? fmaxf(m1 / d1, 0.f) : 0.f;
}

// ---------------------------------------------------------------------------
extern "C" void kernel_launch(void* const* d_in, const int* in_sizes, int n_in,
                              void* d_out, int out_size) {
    const float* x       = (const float*)d_in[0];
    const int*   ei      = (const int*)  d_in[1];
    const int*   ntypes  = (const int*)  d_in[2];
    const int*   etypes  = (const int*)  d_in[3];
    const float* eattr   = (const float*)d_in[4];
    const float* het_W   = (const float*)d_in[5];
    const float* het_b   = (const float*)d_in[6];
    const float* etab    = (const float*)d_in[7];
    const float* eattr_W = (const float*)d_in[8];
    const float* att_W   = (const float*)d_in[9];
    const float* lin_W   = (const float*)d_in[10];
    float* out = (float*)d_out;

    k_init<<<(NN + 255) / 256, 256>>>();
    k_cnt<<<(EE + 255) / 256, 256>>>(ei);

    dim3 gh(NT_, (NN + NPB - 1) / NPB);
    k_het<<<gh, 256>>>(x, ntypes, het_W, het_b, att_W, lin_W);

    const int NB = (NN + 1023) / 1024;
    k_scan1<<<NB, 1024>>>();
    k_scan3<<<NB, 1024>>>();

    k_scatter<<<(EE + 255) / 256, 256>>>(ei, etypes);

    k_agg<<<(NN * 32 + 255) / 256, 256>>>(eattr, etab, eattr_W, att_W, lin_W, out);
}

// round 5
// speedup vs baseline: 2.7826x; 1.0706x over previous
#include <cuda_runtime.h>

#define NN     50000
#define EE     1600000
#define IN_F   128
#define OUT_F  32
#define NT_    20
#define ET_    4
#define ETE_   16
#define EAE_   16
#define ED_    16
#define SLOPE  0.2f

// ---- scratch (device globals; allocation-free) ----
__device__ float     g_hm[NN * OUT_F];   // 6.4 MB : h @ lin_W[0:32] (L2-resident)
__device__ float     g_att[NN * 4];      // 0.8 MB : {ai0, ai1, aj0, aj1}
__device__ long long g_erec[EE];         // 12.8 MB: dst-sorted {e, src|et<<16}
__device__ int       g_cnt[NN];
__device__ int       g_off[NN];
__device__ int       g_woff[NN];
__device__ int       g_bsum[64];

__device__ __forceinline__ float lrelu(float v) { return v > 0.f ? v : SLOPE * v; }

// ---------------------------------------------------------------------------
__global__ void k_init() {
    int i = blockIdx.x * blockDim.x + threadIdx.x;
    if (i < NN) g_cnt[i] = 0;
}

__global__ void k_cnt(const int* __restrict__ ei) {
    int e = blockIdx.x * blockDim.x + threadIdx.x;
    if (e < EE) atomicAdd(&g_cnt[ei[EE + e]], 1);
}

// ---------------------------------------------------------------------------
// HeteroLinear + node-side precomputes (h never leaves registers):
//   hm = h @ lin_W[0:32];  ai_h = h.att_W[0:32,h];  aj_h = h.att_W[32:64,h]
// ---------------------------------------------------------------------------
#define NPB 1024
__global__ void k_het(const float* __restrict__ x, const int* __restrict__ ntypes,
                      const float* __restrict__ het_W, const float* __restrict__ het_b,
                      const float* __restrict__ att_W, const float* __restrict__ lin_W) {
    __shared__ float Ws[IN_F * OUT_F];
    __shared__ float bs[OUT_F];
    __shared__ float aWs[64 * 2];
    __shared__ float lWs[OUT_F * OUT_F];
    __shared__ int   list[NPB];
    __shared__ int   cnt;

    const int t    = blockIdx.x;
    const int base = blockIdx.y * NPB;
    const int tid  = threadIdx.x;

    for (int i = tid; i < IN_F * OUT_F; i += blockDim.x) Ws[i] = het_W[t * IN_F * OUT_F + i];
    for (int i = tid; i < OUT_F * OUT_F; i += blockDim.x) lWs[i] = lin_W[i];
    if (tid < 128)   aWs[tid] = att_W[tid];
    if (tid < OUT_F) bs[tid] = het_b[t * OUT_F + tid];
    if (tid == 0)    cnt = 0;
    __syncthreads();

    const int end = min(base + NPB, NN);
    for (int n = base + tid; n < end; n += blockDim.x)
        if (ntypes[n] == t) { int p = atomicAdd(&cnt, 1); list[p] = n; }
    __syncthreads();

    const int lane = tid & 31, warp = tid >> 5, nw = blockDim.x >> 5;
    for (int i = warp; i < cnt; i += nw) {
        const int n = list[i];
        const float* xr = x + (size_t)n * IN_F;
        float x0 = xr[lane], x1 = xr[32 + lane], x2 = xr[64 + lane], x3 = xr[96 + lane];
        float acc = bs[lane];
        #pragma unroll
        for (int k = 0; k < 32; k++) {
            acc += __shfl_sync(0xffffffffu, x0, k) * Ws[ k        * OUT_F + lane];
            acc += __shfl_sync(0xffffffffu, x1, k) * Ws[(32 + k)  * OUT_F + lane];
            acc += __shfl_sync(0xffffffffu, x2, k) * Ws[(64 + k)  * OUT_F + lane];
            acc += __shfl_sync(0xffffffffu, x3, k) * Ws[(96 + k)  * OUT_F + lane];
        }
        float ai0 = acc * aWs[lane * 2 + 0], ai1 = acc * aWs[lane * 2 + 1];
        float aj0 = acc * aWs[64 + lane * 2 + 0], aj1 = acc * aWs[64 + lane * 2 + 1];
        #pragma unroll
        for (int o = 16; o > 0; o >>= 1) {
            ai0 += __shfl_xor_sync(0xffffffffu, ai0, o);
            ai1 += __shfl_xor_sync(0xffffffffu, ai1, o);
            aj0 += __shfl_xor_sync(0xffffffffu, aj0, o);
            aj1 += __shfl_xor_sync(0xffffffffu, aj1, o);
        }
        float hm = 0.f;
        #pragma unroll
        for (int k = 0; k < 32; k++)
            hm += __shfl_sync(0xffffffffu, acc, k) * lWs[k * OUT_F + lane];
        g_hm[n * OUT_F + lane] = hm;
        if (lane == 0)
            *reinterpret_cast<float4*>(&g_att[n * 4]) = make_float4(ai0, ai1, aj0, aj1);
    }
}

// ---------------------------------------------------------------------------
// Scan
// ---------------------------------------------------------------------------
__global__ void k_scan1() {
    __shared__ int ws[32];
    const int b = blockIdx.x, tid = threadIdx.x;
    const int i = b * 1024 + tid;
    int v = (i < NN) ? g_cnt[i] : 0;
    const int lane = tid & 31, w = tid >> 5;
    int incl = v;
    #pragma unroll
    for (int o = 1; o < 32; o <<= 1) {
        int t = __shfl_up_sync(0xffffffffu, incl, o);
        if (lane >= o) incl += t;
    }
    if (lane == 31) ws[w] = incl;
    __syncthreads();
    if (w == 0) {
        int s = ws[lane];
        int si = s;
        #pragma unroll
        for (int o = 1; o < 32; o <<= 1) {
            int t = __shfl_up_sync(0xffffffffu, si, o);
            if (lane >= o) si += t;
        }
        ws[lane] = si - s;
        if (lane == 31) g_bsum[b] = si;
    }
    __syncthreads();
    if (i < NN) g_off[i] = incl - v + ws[w];
}

__global__ void k_scan3() {
    const int b = blockIdx.x;
    __shared__ int boff;
    if (threadIdx.x == 0) {
        int s = 0;
        for (int i = 0; i < b; i++) s += g_bsum[i];
        boff = s;
    }
    __syncthreads();
    const int i = b * 1024 + threadIdx.x;
    if (i < NN) {
        const int v = g_off[i] + boff;
        g_off[i] = v;
        g_woff[i] = v;
    }
}

// ---------------------------------------------------------------------------
__global__ void k_scatter(const int* __restrict__ ei, const int* __restrict__ etypes) {
    const int e = blockIdx.x * blockDim.x + threadIdx.x;
    if (e >= EE) return;
    const int src = ei[e];
    const int d   = ei[EE + e];
    const int et  = etypes[e];
    const int pos = atomicAdd(&g_woff[d], 1);
    g_erec[pos] = ((long long)e << 32) | (unsigned)(src | (et << 16));
}

// ---------------------------------------------------------------------------
// Fused edge+aggregate with depth-2 software pipeline. One warp per dst node.
// ---------------------------------------------------------------------------
struct Ebuf {
    long long rec;
    float4 va, vb, vc, vd;
    float  hmv;
    float2 asr;
};

__device__ __forceinline__ void fetch_edge(Ebuf& b, const long long* __restrict__ erecp,
                                           int idx, int c,
                                           const float* __restrict__ eattr, int lane, int cl) {
    b.rec = 0; b.hmv = 0.f; b.asr = make_float2(0.f, 0.f);
    b.va = b.vb = b.vc = b.vd = make_float4(0.f, 0.f, 0.f, 0.f);
    if (idx < c) {
        b.rec = __ldg(erecp + idx);
        const size_t e = (size_t)(b.rec >> 32);
        const int sp = (int)b.rec, src = sp & 0xFFFF;
        const float4* er = reinterpret_cast<const float4*>(&eattr[e * ED_]);
        b.va = __ldg(er); b.vb = __ldg(er + 1); b.vc = __ldg(er + 2); b.vd = __ldg(er + 3);
        b.hmv = __ldg(&g_hm[src * OUT_F + lane]);
        b.asr = *reinterpret_cast<const float2*>(&g_att[src * 4 + 2]);
    }
}

__device__ __forceinline__ void proc_edge(const Ebuf& b, const float* __restrict__ Wr,
                                          float awh, float2 adt, const float* __restrict__ cet,
                                          float& acc0, float& acc1, float& wea0, float& wea1,
                                          float& d0, float& d1) {
    float z = b.va.x * Wr[0]  + b.va.y * Wr[1]  + b.va.z * Wr[2]  + b.va.w * Wr[3]
            + b.vb.x * Wr[4]  + b.vb.y * Wr[5]  + b.vb.z * Wr[6]  + b.vb.w * Wr[7]
            + b.vc.x * Wr[8]  + b.vc.y * Wr[9]  + b.vc.z * Wr[10] + b.vc.w * Wr[11]
            + b.vd.x * Wr[12] + b.vd.y * Wr[13] + b.vd.z * Wr[14] + b.vd.w * Wr[15];
    const float ea = lrelu(z);

    float v = ea * awh;
    v += __shfl_xor_sync(0xffffffffu, v, 8);
    v += __shfl_xor_sync(0xffffffffu, v, 4);
    v += __shfl_xor_sync(0xffffffffu, v, 2);
    v += __shfl_xor_sync(0xffffffffu, v, 1);
    const float p0 = __shfl_sync(0xffffffffu, v, 0);
    const float p1 = __shfl_sync(0xffffffffu, v, 16);

    const int et = ((int)b.rec >> 16) & 3;
    const float l0 = adt.x + b.asr.x + cet[et * 2 + 0] + p0;
    const float l1 = adt.y + b.asr.y + cet[et * 2 + 1] + p1;
    const float a0 = __expf(lrelu(l0));
    const float a1 = __expf(lrelu(l1));

    acc0 += a0 * b.hmv;  acc1 += a1 * b.hmv;
    wea0 += a0 * ea;     wea1 += a1 * ea;
    d0   += a0;          d1   += a1;
}

__global__ void __launch_bounds__(256) k_agg(
        const float* __restrict__ eattr, const float* __restrict__ etab,
        const float* __restrict__ eattr_W, const float* __restrict__ att_W,
        const float* __restrict__ lin_W, float* __restrict__ out) {
    __shared__ float lW2[EAE_ * OUT_F];  // lin_W rows 32..47
    __shared__ float cet[ET_ * 2];

    const int tid  = threadIdx.x;
    const int lane = tid & 31;
    const int cl   = lane & 15;

    for (int i = tid; i < EAE_ * OUT_F; i += blockDim.x) lW2[i] = lin_W[OUT_F * OUT_F + i];
    if (tid < ET_ * 2) {
        const int et = tid >> 1, h = tid & 1;
        float s = 0.f;
        for (int j = 0; j < ETE_; j++)
            s += lrelu(etab[et * ETE_ + j]) * att_W[(64 + j) * 2 + h];
        cet[tid] = s;
    }
    __syncthreads();

    float Wr[ED_];
    #pragma unroll
    for (int k = 0; k < ED_; k++) Wr[k] = eattr_W[k * EAE_ + cl];
    const float awh = att_W[160 + cl * 2 + (lane >> 4)];

    const int n = blockIdx.x * (blockDim.x >> 5) + (tid >> 5);
    if (n >= NN) return;

    const int off = g_off[n], c = g_cnt[n];
    const float2 adt = *reinterpret_cast<const float2*>(&g_att[n * 4]);

    float acc0 = 0.f, acc1 = 0.f, wea0 = 0.f, wea1 = 0.f, d0 = 0.f, d1 = 0.f;

    const long long* erecp = &g_erec[off];
    Ebuf b0, b1;
    fetch_edge(b0, erecp, 0, c, eattr, lane, cl);
    fetch_edge(b1, erecp, 1, c, eattr, lane, cl);

    int i = 0;
    for (; i + 1 < c; i += 2) {
        proc_edge(b0, Wr, awh, adt, cet, acc0, acc1, wea0, wea1, d0, d1);
        fetch_edge(b0, erecp, i + 2, c, eattr, lane, cl);
        proc_edge(b1, Wr, awh, adt, cet, acc0, acc1, wea0, wea1, d0, d1);
        fetch_edge(b1, erecp, i + 3, c, eattr, lane, cl);
    }
    if (i < c)
        proc_edge(b0, Wr, awh, adt, cet, acc0, acc1, wea0, wea1, d0, d1);

    float m0 = acc0, m1 = acc1;
    #pragma unroll
    for (int k = 0; k < EAE_; k++) {
        m0 += __shfl_sync(0xffffffffu, wea0, k) * lW2[k * OUT_F + lane];
        m1 += __shfl_sync(0xffffffffu, wea1, k) * lW2[k * OUT_F + lane];
    }
    out[(size_t)n * 64 + lane]      = c ? fmaxf(m0 / d0, 0.f) : 0.f;
    out[(size_t)n * 64 + 32 + lane] = c ? fmaxf(m1 / d1, 0.f) : 0.f;
}

// ---------------------------------------------------------------------------
extern "C" void kernel_launch(void* const* d_in, const int* in_sizes, int n_in,
                              void* d_out, int out_size) {
    const float* x       = (const float*)d_in[0];
    const int*   ei      = (const int*)  d_in[1];
    const int*   ntypes  = (const int*)  d_in[2];
    const int*   etypes  = (const int*)  d_in[3];
    const float* eattr   = (const float*)d_in[4];
    const float* het_W   = (const float*)d_in[5];
    const float* het_b   = (const float*)d_in[6];
    const float* etab    = (const float*)d_in[7];
    const float* eattr_W = (const float*)d_in[8];
    const float* att_W   = (const float*)d_in[9];
    const float* lin_W   = (const float*)d_in[10];
    float* out = (float*)d_out;

    k_init<<<(NN + 255) / 256, 256>>>();
    k_cnt<<<(EE + 255) / 256, 256>>>(ei);

    dim3 gh(NT_, (NN + NPB - 1) / NPB);
    k_het<<<gh, 256>>>(x, ntypes, het_W, het_b, att_W, lin_W);

    const int NB = (NN + 1023) / 1024;
    k_scan1<<<NB, 1024>>>();
    k_scan3<<<NB, 1024>>>();

    k_scatter<<<(EE + 255) / 256, 256>>>(ei, etypes);

    k_agg<<<(NN * 32 + 255) / 256, 256>>>(eattr, etab, eattr_W, att_W, lin_W, out);
}